// round 10
// baseline (speedup 1.0000x reference)
#include <cuda_runtime.h>
#include <cuda_fp16.h>
#include <cstdint>

#define TOKENS 4096
#define DIN    1024
#define DHID   4096
#define DOUT   1024
#define NEXP   8

// ---------------- device scratch ----------------
__device__ __half g_xh [TOKENS * DIN];                          // x fp16 [M][K]
__device__ __half g_B1 [(NEXP + 1) * (size_t)DIN * DHID];       // W1 [e][K][N] + Wg1 (e=8), fp16
__device__ __half g_W2h[(size_t)NEXP * DHID * DOUT];            // W2 [e][K][N] fp16
__device__ __half g_H  [(NEXP + 1) * (size_t)TOKENS * DHID];    // H[e][b][h]; slot 8 = gating hidden
__device__ float  g_gate[TOKENS * NEXP];
__device__ float  g_gb2 [TOKENS * DOUT];                        // gate @ b2
__device__ float  g_part[NEXP * (size_t)TOKENS * DOUT];         // split-K partials

// ---------------- PTX helpers ----------------
__device__ __forceinline__ void cp_async16(unsigned dst, const void* src) {
    asm volatile("cp.async.cg.shared.global [%0], [%1], 16;\n" :: "r"(dst), "l"(src));
}
__device__ __forceinline__ void cp_commit() {
    asm volatile("cp.async.commit_group;\n" ::: "memory");
}
__device__ __forceinline__ void cp_wait0() {
    asm volatile("cp.async.wait_group 0;\n" ::: "memory");
}
__device__ __forceinline__ void ldsm_x4(uint32_t* r, unsigned addr) {
    asm volatile("ldmatrix.sync.aligned.m8n8.x4.shared.b16 {%0,%1,%2,%3}, [%4];\n"
                 : "=r"(r[0]), "=r"(r[1]), "=r"(r[2]), "=r"(r[3]) : "r"(addr));
}
__device__ __forceinline__ void ldsm_x4_t(uint32_t* r, unsigned addr) {
    asm volatile("ldmatrix.sync.aligned.m8n8.x4.trans.shared.b16 {%0,%1,%2,%3}, [%4];\n"
                 : "=r"(r[0]), "=r"(r[1]), "=r"(r[2]), "=r"(r[3]) : "r"(addr));
}
__device__ __forceinline__ void mma16816(float* c, const uint32_t* a, uint32_t b0, uint32_t b1) {
    asm volatile("mma.sync.aligned.m16n8k16.row.col.f32.f16.f16.f32 "
                 "{%0,%1,%2,%3},{%4,%5,%6,%7},{%8,%9},{%0,%1,%2,%3};\n"
                 : "+f"(c[0]), "+f"(c[1]), "+f"(c[2]), "+f"(c[3])
                 : "r"(a[0]), "r"(a[1]), "r"(a[2]), "r"(a[3]), "r"(b0), "r"(b1));
}

// ---------------- fp32 -> fp16 convert ----------------
__global__ void cvt_f32_f16(const float* __restrict__ src, __half* __restrict__ dst, int n) {
    int i = (blockIdx.x * blockDim.x + threadIdx.x) * 4;
    if (i >= n) return;
    float4 v = *(const float4*)(src + i);
    *(__half2*)(dst + i)     = __floats2half2_rn(v.x, v.y);
    *(__half2*)(dst + i + 2) = __floats2half2_rn(v.z, v.w);
}

// ---------------- gating softmax ----------------
__global__ void __launch_bounds__(256) gate_kernel(
    const __half* __restrict__ Hg, const float* __restrict__ Wg2,
    const float* __restrict__ bg2, float* __restrict__ gate)
{
    extern __shared__ float sW[];   // [8][4096] transposed
    const int tid = threadIdx.x;
    for (int i = tid; i < DHID * NEXP; i += 256) {
        int k = i >> 3, j = i & 7;
        sW[j * DHID + k] = Wg2[i];
    }
    __syncthreads();
    const int warp = tid >> 5, lane = tid & 31;
    const int row = blockIdx.x * 8 + warp;
    const __half2* h2 = (const __half2*)(Hg + (long long)row * DHID);
    float a[NEXP];
#pragma unroll
    for (int j = 0; j < NEXP; j++) a[j] = 0.f;
    for (int k2 = lane; k2 < DHID / 2; k2 += 32) {
        float2 xv = __half22float2(h2[k2]);
#pragma unroll
        for (int j = 0; j < NEXP; j++)
            a[j] += xv.x * sW[j * DHID + 2 * k2] + xv.y * sW[j * DHID + 2 * k2 + 1];
    }
#pragma unroll
    for (int j = 0; j < NEXP; j++)
#pragma unroll
        for (int o = 16; o > 0; o >>= 1) a[j] += __shfl_xor_sync(0xffffffffu, a[j], o);
    float m = -1e30f;
#pragma unroll
    for (int j = 0; j < NEXP; j++) { a[j] += bg2[j]; m = fmaxf(m, a[j]); }
    float ex[NEXP], s = 0.f;
#pragma unroll
    for (int j = 0; j < NEXP; j++) { ex[j] = expf(a[j] - m); s += ex[j]; }
    if (lane < NEXP) gate[row * NEXP + lane] = ex[lane] / s;
}

// gb2[b][o] = sum_j gate[b][j] * b2[j][o]
__global__ void __launch_bounds__(256) gb2_kernel(
    const float* __restrict__ gate, const float* __restrict__ b2, float* __restrict__ gb2)
{
    int b = blockIdx.x;
    float g[NEXP];
#pragma unroll
    for (int j = 0; j < NEXP; j++) g[j] = gate[b * NEXP + j];
    for (int o = threadIdx.x; o < DOUT; o += 256) {
        float s = 0.f;
#pragma unroll
        for (int j = 0; j < NEXP; j++) s += g[j] * b2[j * DOUT + o];
        gb2[b * DOUT + o] = s;
    }
}

// out = gb2 + sum_e part[e]
__global__ void __launch_bounds__(256) reduce_kernel(
    const float* __restrict__ part, const float* __restrict__ gb2, float* __restrict__ out)
{
    const long long i = ((long long)blockIdx.x * 256 + threadIdx.x) * 4;
    float4 s = *(const float4*)(gb2 + i);
#pragma unroll
    for (int e = 0; e < NEXP; e++) {
        float4 p = *(const float4*)(part + (long long)e * TOKENS * DOUT + i);
        s.x += p.x; s.y += p.y; s.z += p.z; s.w += p.w;
    }
    *(float4*)(out + i) = s;
}

// ---------------- fused fp16 GEMM: 128x256x64 CTA tile, 64x64 warp tile ----------------
// A: [M][K] row-major fp16.  B: [K][N] row-major fp16 (natural layout).
// MODE 0: C = relu(A@B + bias)                -> fp16   (gating layer-1)
// MODE 1: C = gate[b,e]*relu(A@B + bias_e)    -> fp16   (expert layer-1, z=e)
// MODE 2: C = A_e@B_e                         -> fp32   (layer-2 partial, z=e, K=4096)
constexpr int BM = 128, BN = 256, BK = 64, STAGES = 2;
constexpr int ASTR = BK + 8;          // 72 halves  (144B rows; row shift 16B mod 128 -> conflict-free)
constexpr int BSTR = BN + 8;          // 264 halves (528B rows; shift 16B mod 128 -> conflict-free)
constexpr int A_TILE = BM * ASTR;     // halves (18,432 B)
constexpr int B_TILE = BK * BSTR;     // halves (33,792 B)
constexpr int SMEM_BYTES = STAGES * (A_TILE + B_TILE) * 2;   // 104,448 B -> 1 CTA/SM

template <int MODE>
__global__ void __launch_bounds__(256, 1) moe_gemm(
    const __half* __restrict__ Abase, long long aSlab, int lda,
    const __half* __restrict__ Bbase, long long bStride, int ldb,
    const float* __restrict__ biasBase, long long biasStride,
    const float* __restrict__ gate,
    void* __restrict__ Cbase, long long cStride, int ldc,
    int K)
{
    extern __shared__ __half sm_[];
    __half* As = sm_;
    __half* Bs = sm_ + STAGES * A_TILE;

    const int tid  = threadIdx.x;
    const int lane = tid & 31;
    const int warp = tid >> 5;
    const int wm = warp >> 2, wn = warp & 3;   // 2x4 warp grid, warp tile 64x64
    const int bm0 = blockIdx.y * BM;
    const int bn0 = blockIdx.x * BN;
    const int e   = blockIdx.z;

    const __half* Amat = Abase + (MODE == 2 ? (long long)e * aSlab : 0LL);
    const __half* Bmat = Bbase + (long long)e * bStride;

    const unsigned sA0 = (unsigned)__cvta_generic_to_shared(As);
    const unsigned sB0 = (unsigned)__cvta_generic_to_shared(Bs);

    float acc[4][8][4];
#pragma unroll
    for (int a = 0; a < 4; a++)
#pragma unroll
        for (int b = 0; b < 8; b++)
#pragma unroll
            for (int c = 0; c < 4; c++) acc[a][b][c] = 0.f;

    const int KT = K / BK;

    auto load_tile = [&](int kt, int buf) {
        const int k0 = kt * BK;
        const __half* aSrc = Amat + k0;
        const __half* bSrc = Bmat + (long long)k0 * ldb + bn0;
        const unsigned da = sA0 + buf * (A_TILE * 2);
        const unsigned db = sB0 + buf * (B_TILE * 2);
        // A: 128 rows x 8 chunks of 16B = 1024 cp.async
#pragma unroll
        for (int i = 0; i < 4; i++) {
            int c = tid + i * 256;
            int r = c >> 3, c8 = (c & 7) << 3;
            cp_async16(da + (unsigned)(r * ASTR + c8) * 2,
                       aSrc + (long long)(bm0 + r) * lda + c8);
        }
        // B: 64 rows x 32 chunks of 16B = 2048 cp.async
#pragma unroll
        for (int i = 0; i < 8; i++) {
            int c = tid + i * 256;
            int r = c >> 5, c32 = (c & 31) << 3;
            cp_async16(db + (unsigned)(r * BSTR + c32) * 2,
                       bSrc + (long long)r * ldb + c32);
        }
        cp_commit();
    };

    load_tile(0, 0);

    const int lr = lane & 15;
    const int lc = (lane >> 4) << 3;

    for (int kt = 0; kt < KT; kt++) {
        cp_wait0();
        __syncthreads();
        const int nt = kt + 1;
        if (nt < KT) load_tile(nt, nt & 1);   // in flight during compute(kt)

        const int buf = kt & 1;
        const unsigned aB = sA0 + buf * (A_TILE * 2);
        const unsigned bB = sB0 + buf * (B_TILE * 2);
#pragma unroll
        for (int ks = 0; ks < BK / 16; ks++) {
            uint32_t af[4][4];
#pragma unroll
            for (int mb = 0; mb < 4; mb++)
                ldsm_x4(af[mb], aB + (unsigned)((wm * 64 + mb * 16 + lr) * ASTR + ks * 16 + lc) * 2);
#pragma unroll
            for (int nb = 0; nb < 4; nb++) {
                uint32_t bf[4];
                ldsm_x4_t(bf, bB + (unsigned)((ks * 16 + lr) * BSTR + wn * 64 + nb * 16 + lc) * 2);
#pragma unroll
                for (int mb = 0; mb < 4; mb++) {
                    mma16816(acc[mb][2 * nb],     af[mb], bf[0], bf[1]);
                    mma16816(acc[mb][2 * nb + 1], af[mb], bf[2], bf[3]);
                }
            }
        }
    }

    // -------- epilogue --------
    const int g  = lane >> 2;
    const int tg = lane & 3;

    if constexpr (MODE == 0 || MODE == 1) {
        __half* C = (__half*)Cbase + (long long)e * cStride;
        const float* bias = biasBase + (long long)e * biasStride;
#pragma unroll
        for (int mb = 0; mb < 4; mb++)
#pragma unroll
            for (int i = 0; i < 2; i++) {
                const int row = bm0 + wm * 64 + mb * 16 + g + i * 8;
                float gv = 1.f;
                if constexpr (MODE == 1) gv = gate[row * NEXP + e];
#pragma unroll
                for (int nb = 0; nb < 8; nb++) {
                    const int col = bn0 + wn * 64 + nb * 8 + tg * 2;
                    float v0 = fmaxf(acc[mb][nb][2 * i + 0] + bias[col],     0.f) * gv;
                    float v1 = fmaxf(acc[mb][nb][2 * i + 1] + bias[col + 1], 0.f) * gv;
                    *(__half2*)(C + (long long)row * ldc + col) = __floats2half2_rn(v0, v1);
                }
            }
    } else {
        float* C = (float*)Cbase + (long long)e * cStride;
#pragma unroll
        for (int mb = 0; mb < 4; mb++)
#pragma unroll
            for (int i = 0; i < 2; i++) {
                const int row = bm0 + wm * 64 + mb * 16 + g + i * 8;
#pragma unroll
                for (int nb = 0; nb < 8; nb++) {
                    const int col = bn0 + wn * 64 + nb * 8 + tg * 2;
                    float2 o;
                    o.x = acc[mb][nb][2 * i + 0];
                    o.y = acc[mb][nb][2 * i + 1];
                    *(float2*)(C + (long long)row * ldc + col) = o;
                }
            }
    }
}

// ---------------- launch ----------------
extern "C" void kernel_launch(void* const* d_in, const int* in_sizes, int n_in,
                              void* d_out, int out_size)
{
    const float* x   = (const float*)d_in[0];
    const float* W1  = (const float*)d_in[1];
    const float* b1  = (const float*)d_in[2];
    const float* W2  = (const float*)d_in[3];
    const float* b2  = (const float*)d_in[4];
    const float* Wg1 = (const float*)d_in[5];
    const float* bg1 = (const float*)d_in[6];
    const float* Wg2 = (const float*)d_in[7];
    const float* bg2 = (const float*)d_in[8];

    __half *xh, *B1, *W2h, *H;
    float *gate, *gb2, *part;
    cudaGetSymbolAddress((void**)&xh,   g_xh);
    cudaGetSymbolAddress((void**)&B1,   g_B1);
    cudaGetSymbolAddress((void**)&W2h,  g_W2h);
    cudaGetSymbolAddress((void**)&H,    g_H);
    cudaGetSymbolAddress((void**)&gate, g_gate);
    cudaGetSymbolAddress((void**)&gb2,  g_gb2);
    cudaGetSymbolAddress((void**)&part, g_part);

    cudaFuncSetAttribute(moe_gemm<0>, cudaFuncAttributeMaxDynamicSharedMemorySize, SMEM_BYTES);
    cudaFuncSetAttribute(moe_gemm<1>, cudaFuncAttributeMaxDynamicSharedMemorySize, SMEM_BYTES);
    cudaFuncSetAttribute(moe_gemm<2>, cudaFuncAttributeMaxDynamicSharedMemorySize, SMEM_BYTES);
    cudaFuncSetAttribute(gate_kernel, cudaFuncAttributeMaxDynamicSharedMemorySize, DHID * NEXP * 4);

    // fp32 -> fp16 converts (weights stay in natural [K][N] layout)
    cvt_f32_f16<<<TOKENS * DIN / 1024, 256>>>(x, xh, TOKENS * DIN);
    cvt_f32_f16<<<NEXP * DIN * DHID / 1024, 256>>>(W1, B1, NEXP * DIN * DHID);
    cvt_f32_f16<<<DIN * DHID / 1024, 256>>>(Wg1, B1 + (long long)NEXP * DIN * DHID, DIN * DHID);
    cvt_f32_f16<<<NEXP * DHID * DOUT / 1024, 256>>>(W2, W2h, NEXP * DHID * DOUT);

    // 1) gating hidden: Hg = relu(x @ Wg1 + bg1)   (slot 8)
    moe_gemm<0><<<dim3(DHID / BN, TOKENS / BM, 1), 256, SMEM_BYTES>>>(
        xh, 0, DIN,
        B1 + (long long)NEXP * DIN * DHID, 0, DHID,
        bg1, 0, nullptr,
        H + (long long)NEXP * TOKENS * DHID, 0, DHID, DIN);

    // 2) gates + gate@b2
    gate_kernel<<<TOKENS / 8, 256, DHID * NEXP * 4>>>(
        H + (long long)NEXP * TOKENS * DHID, Wg2, bg2, gate);
    gb2_kernel<<<TOKENS, 256>>>(gate, b2, gb2);

    // 3) expert layer-1 (batched over e): H[e] = gate[b,e]*relu(x @ W1[e] + b1[e])
    moe_gemm<1><<<dim3(DHID / BN, TOKENS / BM, NEXP), 256, SMEM_BYTES>>>(
        xh, 0, DIN,
        B1, (long long)DIN * DHID, DHID,
        b1, DHID, gate,
        H, (long long)TOKENS * DHID, DHID, DIN);

    // 4) layer-2 split-K over experts: part[e] = H[e] @ W2[e]
    moe_gemm<2><<<dim3(DOUT / BN, TOKENS / BM, NEXP), 256, SMEM_BYTES>>>(
        H, (long long)TOKENS * DHID, DHID,
        W2h, (long long)DHID * DOUT, DOUT,
        nullptr, 0, nullptr,
        part, (long long)TOKENS * DOUT, DOUT, DHID);

    // 5) out = gb2 + sum_e part[e]
    reduce_kernel<<<TOKENS * DOUT / 1024, 256>>>(part, gb2, (float*)d_out);
}

// round 11
// speedup vs baseline: 1.0688x; 1.0688x over previous
#include <cuda_runtime.h>
#include <cuda_fp16.h>
#include <cstdint>

#define TOKENS 4096
#define DIN    1024
#define DHID   4096
#define DOUT   1024
#define NEXP   8

// ---------------- device scratch ----------------
__device__ __half g_xh [TOKENS * DIN];                          // x fp16 [M][K]
__device__ __half g_B1 [(NEXP + 1) * (size_t)DIN * DHID];       // W1 [e][K][N] + Wg1 (e=8), fp16
__device__ __half g_W2h[(size_t)NEXP * DHID * DOUT];            // W2 [e][K][N] fp16
__device__ __half g_H  [(NEXP + 1) * (size_t)TOKENS * DHID];    // H[e][b][h]; slot 8 = gating hidden
__device__ float  g_gate[TOKENS * NEXP];
__device__ float  g_gb2 [TOKENS * DOUT];                        // gate @ b2
__device__ float  g_part[NEXP * (size_t)TOKENS * DOUT];         // split-K partials

// ---------------- PTX helpers ----------------
__device__ __forceinline__ void cp_async16(unsigned dst, const void* src) {
    asm volatile("cp.async.cg.shared.global [%0], [%1], 16;\n" :: "r"(dst), "l"(src));
}
__device__ __forceinline__ void cp_commit() {
    asm volatile("cp.async.commit_group;\n" ::: "memory");
}
__device__ __forceinline__ void cp_wait1() {
    asm volatile("cp.async.wait_group 1;\n" ::: "memory");
}
__device__ __forceinline__ void ldsm_x4(uint32_t* r, unsigned addr) {
    asm volatile("ldmatrix.sync.aligned.m8n8.x4.shared.b16 {%0,%1,%2,%3}, [%4];\n"
                 : "=r"(r[0]), "=r"(r[1]), "=r"(r[2]), "=r"(r[3]) : "r"(addr));
}
__device__ __forceinline__ void ldsm_x4_t(uint32_t* r, unsigned addr) {
    asm volatile("ldmatrix.sync.aligned.m8n8.x4.trans.shared.b16 {%0,%1,%2,%3}, [%4];\n"
                 : "=r"(r[0]), "=r"(r[1]), "=r"(r[2]), "=r"(r[3]) : "r"(addr));
}
__device__ __forceinline__ void mma16816(float* c, const uint32_t* a, uint32_t b0, uint32_t b1) {
    asm volatile("mma.sync.aligned.m16n8k16.row.col.f32.f16.f16.f32 "
                 "{%0,%1,%2,%3},{%4,%5,%6,%7},{%8,%9},{%0,%1,%2,%3};\n"
                 : "+f"(c[0]), "+f"(c[1]), "+f"(c[2]), "+f"(c[3])
                 : "r"(a[0]), "r"(a[1]), "r"(a[2]), "r"(a[3]), "r"(b0), "r"(b1));
}

// ---------------- fp32 -> fp16 convert ----------------
__global__ void cvt_f32_f16(const float* __restrict__ src, __half* __restrict__ dst, int n) {
    int i = (blockIdx.x * blockDim.x + threadIdx.x) * 4;
    if (i >= n) return;
    float4 v = *(const float4*)(src + i);
    *(__half2*)(dst + i)     = __floats2half2_rn(v.x, v.y);
    *(__half2*)(dst + i + 2) = __floats2half2_rn(v.z, v.w);
}

// ---------------- gating softmax ----------------
__global__ void __launch_bounds__(256) gate_kernel(
    const __half* __restrict__ Hg, const float* __restrict__ Wg2,
    const float* __restrict__ bg2, float* __restrict__ gate)
{
    extern __shared__ float sW[];   // [8][4096] transposed
    const int tid = threadIdx.x;
    for (int i = tid; i < DHID * NEXP; i += 256) {
        int k = i >> 3, j = i & 7;
        sW[j * DHID + k] = Wg2[i];
    }
    __syncthreads();
    const int warp = tid >> 5, lane = tid & 31;
    const int row = blockIdx.x * 8 + warp;
    const __half2* h2 = (const __half2*)(Hg + (long long)row * DHID);
    float a[NEXP];
#pragma unroll
    for (int j = 0; j < NEXP; j++) a[j] = 0.f;
    for (int k2 = lane; k2 < DHID / 2; k2 += 32) {
        float2 xv = __half22float2(h2[k2]);
#pragma unroll
        for (int j = 0; j < NEXP; j++)
            a[j] += xv.x * sW[j * DHID + 2 * k2] + xv.y * sW[j * DHID + 2 * k2 + 1];
    }
#pragma unroll
    for (int j = 0; j < NEXP; j++)
#pragma unroll
        for (int o = 16; o > 0; o >>= 1) a[j] += __shfl_xor_sync(0xffffffffu, a[j], o);
    float m = -1e30f;
#pragma unroll
    for (int j = 0; j < NEXP; j++) { a[j] += bg2[j]; m = fmaxf(m, a[j]); }
    float ex[NEXP], s = 0.f;
#pragma unroll
    for (int j = 0; j < NEXP; j++) { ex[j] = expf(a[j] - m); s += ex[j]; }
    if (lane < NEXP) gate[row * NEXP + lane] = ex[lane] / s;
}

// gb2[b][o] = sum_j gate[b][j] * b2[j][o]
__global__ void __launch_bounds__(256) gb2_kernel(
    const float* __restrict__ gate, const float* __restrict__ b2, float* __restrict__ gb2)
{
    int b = blockIdx.x;
    float g[NEXP];
#pragma unroll
    for (int j = 0; j < NEXP; j++) g[j] = gate[b * NEXP + j];
    for (int o = threadIdx.x; o < DOUT; o += 256) {
        float s = 0.f;
#pragma unroll
        for (int j = 0; j < NEXP; j++) s += g[j] * b2[j * DOUT + o];
        gb2[b * DOUT + o] = s;
    }
}

// out = gb2 + sum_e part[e]
__global__ void __launch_bounds__(256) reduce_kernel(
    const float* __restrict__ part, const float* __restrict__ gb2, float* __restrict__ out)
{
    const long long i = ((long long)blockIdx.x * 256 + threadIdx.x) * 4;
    float4 s = *(const float4*)(gb2 + i);
#pragma unroll
    for (int e = 0; e < NEXP; e++) {
        float4 p = *(const float4*)(part + (long long)e * TOKENS * DOUT + i);
        s.x += p.x; s.y += p.y; s.z += p.z; s.w += p.w;
    }
    *(float4*)(out + i) = s;
}

// ---------------- fused fp16 GEMM (R8 core + register-pipelined fragments) --------
// A: [M][K] row-major fp16.  B: [K][N] row-major fp16.
// MODE 0: C = relu(A@B + bias)                -> fp16   (gating layer-1)
// MODE 1: C = gate[b,e]*relu(A@B + bias_e)    -> fp16   (expert layer-1, z=e)
// MODE 2: C = A_e@B_e                         -> fp32   (layer-2 partial, z=e, K=4096)
constexpr int BM = 128, BN = 128, BK = 64, STAGES = 3;
constexpr int ASTR = BK + 8;          // 72 halves
constexpr int BSTR = BN + 8;          // 136 halves
constexpr int A_TILE = BM * ASTR;     // halves
constexpr int B_TILE = BK * BSTR;
constexpr int SMEM_BYTES = STAGES * (A_TILE + B_TILE) * 2;   // 107,520 B

template <int MODE>
__global__ void __launch_bounds__(256) moe_gemm(
    const __half* __restrict__ Abase, long long aSlab, int lda,
    const __half* __restrict__ Bbase, long long bStride, int ldb,
    const float* __restrict__ biasBase, long long biasStride,
    const float* __restrict__ gate,
    void* __restrict__ Cbase, long long cStride, int ldc,
    int K)
{
    extern __shared__ __half sm_[];
    __half* As = sm_;
    __half* Bs = sm_ + STAGES * A_TILE;

    const int tid  = threadIdx.x;
    const int lane = tid & 31;
    const int warp = tid >> 5;
    const int wm = warp >> 1, wn = warp & 1;   // 4x2 warp grid, warp tile 32x64
    const int bm0 = blockIdx.y * BM;
    const int bn0 = blockIdx.x * BN;
    const int e   = blockIdx.z;

    const __half* Amat = Abase + (MODE == 2 ? (long long)e * aSlab : 0LL);
    const __half* Bmat = Bbase + (long long)e * bStride;

    const unsigned sA0 = (unsigned)__cvta_generic_to_shared(As);
    const unsigned sB0 = (unsigned)__cvta_generic_to_shared(Bs);

    float acc[2][8][4];
#pragma unroll
    for (int a = 0; a < 2; a++)
#pragma unroll
        for (int b = 0; b < 8; b++)
#pragma unroll
            for (int c = 0; c < 4; c++) acc[a][b][c] = 0.f;

    const int KT = K / BK;

    auto load_tile = [&](int kt, int buf) {
        const int k0 = kt * BK;
        const __half* aSrc = Amat + k0;
        const __half* bSrc = Bmat + (long long)k0 * ldb + bn0;
        const unsigned da = sA0 + buf * (A_TILE * 2);
        const unsigned db = sB0 + buf * (B_TILE * 2);
#pragma unroll
        for (int i = 0; i < 4; i++) {
            int c = tid + i * 256;
            int r = c >> 3, c8 = (c & 7) << 3;
            cp_async16(da + (unsigned)(r * ASTR + c8) * 2,
                       aSrc + (long long)(bm0 + r) * lda + c8);
        }
#pragma unroll
        for (int i = 0; i < 4; i++) {
            int c = tid + i * 256;
            int r = c >> 4, c16 = (c & 15) << 3;
            cp_async16(db + (unsigned)(r * BSTR + c16) * 2,
                       bSrc + (long long)r * ldb + c16);
        }
        cp_commit();
    };

    load_tile(0, 0);
    load_tile(1, 1);

    const int lr = lane & 15;
    const int lc = (lane >> 4) << 3;

    // fragment double buffers (register-level software pipeline)
    uint32_t af[2][2][4];
    uint32_t bf[2][4][4];

    for (int kt = 0; kt < KT; kt++) {
        cp_wait1();
        __syncthreads();
        const int nt = kt + 2;
        if (nt < KT) load_tile(nt, nt % STAGES);
        else         cp_commit();     // empty group keeps wait accounting aligned

        const int buf = kt % STAGES;
        const unsigned aB = sA0 + buf * (A_TILE * 2);
        const unsigned bB = sB0 + buf * (B_TILE * 2);

        // preload ks = 0 fragments
#pragma unroll
        for (int mb = 0; mb < 2; mb++)
            ldsm_x4(af[0][mb], aB + (unsigned)((wm * 32 + mb * 16 + lr) * ASTR + lc) * 2);
#pragma unroll
        for (int nb = 0; nb < 4; nb++)
            ldsm_x4_t(bf[0][nb], bB + (unsigned)(lr * BSTR + wn * 64 + nb * 16 + lc) * 2);

#pragma unroll
        for (int ks = 0; ks < BK / 16; ks++) {
            const int cur = ks & 1, nxt = cur ^ 1;
            if (ks < BK / 16 - 1) {   // issue next ks's fragments ahead of the MMA burst
#pragma unroll
                for (int mb = 0; mb < 2; mb++)
                    ldsm_x4(af[nxt][mb],
                            aB + (unsigned)((wm * 32 + mb * 16 + lr) * ASTR + (ks + 1) * 16 + lc) * 2);
#pragma unroll
                for (int nb = 0; nb < 4; nb++)
                    ldsm_x4_t(bf[nxt][nb],
                              bB + (unsigned)(((ks + 1) * 16 + lr) * BSTR + wn * 64 + nb * 16 + lc) * 2);
            }
#pragma unroll
            for (int mb = 0; mb < 2; mb++)
#pragma unroll
                for (int nb = 0; nb < 4; nb++) {
                    mma16816(acc[mb][2 * nb],     af[cur][mb], bf[cur][nb][0], bf[cur][nb][1]);
                    mma16816(acc[mb][2 * nb + 1], af[cur][mb], bf[cur][nb][2], bf[cur][nb][3]);
                }
        }
    }

    // -------- epilogue --------
    const int g  = lane >> 2;
    const int tg = lane & 3;

    if constexpr (MODE == 0 || MODE == 1) {
        __half* C = (__half*)Cbase + (long long)e * cStride;
        const float* bias = biasBase + (long long)e * biasStride;
#pragma unroll
        for (int mb = 0; mb < 2; mb++)
#pragma unroll
            for (int i = 0; i < 2; i++) {
                const int row = bm0 + wm * 32 + mb * 16 + g + i * 8;
                float gv = 1.f;
                if constexpr (MODE == 1) gv = gate[row * NEXP + e];
#pragma unroll
                for (int nb = 0; nb < 8; nb++) {
                    const int col = bn0 + wn * 64 + nb * 8 + tg * 2;
                    float v0 = fmaxf(acc[mb][nb][2 * i + 0] + bias[col],     0.f) * gv;
                    float v1 = fmaxf(acc[mb][nb][2 * i + 1] + bias[col + 1], 0.f) * gv;
                    *(__half2*)(C + (long long)row * ldc + col) = __floats2half2_rn(v0, v1);
                }
            }
    } else {
        float* C = (float*)Cbase + (long long)e * cStride;
#pragma unroll
        for (int mb = 0; mb < 2; mb++)
#pragma unroll
            for (int i = 0; i < 2; i++) {
                const int row = bm0 + wm * 32 + mb * 16 + g + i * 8;
#pragma unroll
                for (int nb = 0; nb < 8; nb++) {
                    const int col = bn0 + wn * 64 + nb * 8 + tg * 2;
                    float2 o;
                    o.x = acc[mb][nb][2 * i + 0];
                    o.y = acc[mb][nb][2 * i + 1];
                    *(float2*)(C + (long long)row * ldc + col) = o;
                }
            }
    }
}

// ---------------- launch ----------------
extern "C" void kernel_launch(void* const* d_in, const int* in_sizes, int n_in,
                              void* d_out, int out_size)
{
    const float* x   = (const float*)d_in[0];
    const float* W1  = (const float*)d_in[1];
    const float* b1  = (const float*)d_in[2];
    const float* W2  = (const float*)d_in[3];
    const float* b2  = (const float*)d_in[4];
    const float* Wg1 = (const float*)d_in[5];
    const float* bg1 = (const float*)d_in[6];
    const float* Wg2 = (const float*)d_in[7];
    const float* bg2 = (const float*)d_in[8];

    __half *xh, *B1, *W2h, *H;
    float *gate, *gb2, *part;
    cudaGetSymbolAddress((void**)&xh,   g_xh);
    cudaGetSymbolAddress((void**)&B1,   g_B1);
    cudaGetSymbolAddress((void**)&W2h,  g_W2h);
    cudaGetSymbolAddress((void**)&H,    g_H);
    cudaGetSymbolAddress((void**)&gate, g_gate);
    cudaGetSymbolAddress((void**)&gb2,  g_gb2);
    cudaGetSymbolAddress((void**)&part, g_part);

    cudaFuncSetAttribute(moe_gemm<0>, cudaFuncAttributeMaxDynamicSharedMemorySize, SMEM_BYTES);
    cudaFuncSetAttribute(moe_gemm<1>, cudaFuncAttributeMaxDynamicSharedMemorySize, SMEM_BYTES);
    cudaFuncSetAttribute(moe_gemm<2>, cudaFuncAttributeMaxDynamicSharedMemorySize, SMEM_BYTES);
    cudaFuncSetAttribute(gate_kernel, cudaFuncAttributeMaxDynamicSharedMemorySize, DHID * NEXP * 4);

    // fp32 -> fp16 converts (weights stay in natural [K][N] layout)
    cvt_f32_f16<<<TOKENS * DIN / 1024, 256>>>(x, xh, TOKENS * DIN);
    cvt_f32_f16<<<NEXP * DIN * DHID / 1024, 256>>>(W1, B1, NEXP * DIN * DHID);
    cvt_f32_f16<<<DIN * DHID / 1024, 256>>>(Wg1, B1 + (long long)NEXP * DIN * DHID, DIN * DHID);
    cvt_f32_f16<<<NEXP * DHID * DOUT / 1024, 256>>>(W2, W2h, NEXP * DHID * DOUT);

    // 1) gating hidden: Hg = relu(x @ Wg1 + bg1)   (slot 8)
    moe_gemm<0><<<dim3(DHID / BN, TOKENS / BM, 1), 256, SMEM_BYTES>>>(
        xh, 0, DIN,
        B1 + (long long)NEXP * DIN * DHID, 0, DHID,
        bg1, 0, nullptr,
        H + (long long)NEXP * TOKENS * DHID, 0, DHID, DIN);

    // 2) gates + gate@b2
    gate_kernel<<<TOKENS / 8, 256, DHID * NEXP * 4>>>(
        H + (long long)NEXP * TOKENS * DHID, Wg2, bg2, gate);
    gb2_kernel<<<TOKENS, 256>>>(gate, b2, gb2);

    // 3) expert layer-1 (batched over e): H[e] = gate[b,e]*relu(x @ W1[e] + b1[e])
    moe_gemm<1><<<dim3(DHID / BN, TOKENS / BM, NEXP), 256, SMEM_BYTES>>>(
        xh, 0, DIN,
        B1, (long long)DIN * DHID, DHID,
        b1, DHID, gate,
        H, (long long)TOKENS * DHID, DHID, DIN);

    // 4) layer-2 split-K over experts: part[e] = H[e] @ W2[e]
    moe_gemm<2><<<dim3(DOUT / BN, TOKENS / BM, NEXP), 256, SMEM_BYTES>>>(
        H, (long long)TOKENS * DHID, DHID,
        W2h, (long long)DHID * DOUT, DOUT,
        nullptr, 0, nullptr,
        part, (long long)TOKENS * DOUT, DOUT, DHID);

    // 5) out = gb2 + sum_e part[e]
    reduce_kernel<<<TOKENS * DOUT / 1024, 256>>>(part, gb2, (float*)d_out);
}

// round 12
// speedup vs baseline: 1.1293x; 1.0566x over previous
#include <cuda_runtime.h>
#include <cuda_fp16.h>
#include <cstdint>

#define TOKENS 4096
#define DIN    1024
#define DHID   4096
#define DOUT   1024
#define NEXP   8

// ---------------- device scratch ----------------
__device__ __half g_xh [TOKENS * DIN];                          // x fp16 [M][K]
__device__ __half g_B1 [(NEXP + 1) * (size_t)DIN * DHID];       // W1 [e][K][N] + Wg1 (e=8), fp16
__device__ __half g_W2h[(size_t)NEXP * DHID * DOUT];            // W2 [e][K][N] fp16
__device__ __half g_H  [(NEXP + 1) * (size_t)TOKENS * DHID];    // H[e][b][h]; slot 8 = gating hidden
__device__ float  g_b1a[(NEXP + 1) * DHID];                     // b1 (e<8) ++ bg1 (e=8)
__device__ float  g_gate[TOKENS * NEXP];
__device__ float  g_part[NEXP * (size_t)TOKENS * DOUT];         // split-K partials (no gate)

// ---------------- PTX helpers ----------------
__device__ __forceinline__ void cp_async16(unsigned dst, const void* src) {
    asm volatile("cp.async.cg.shared.global [%0], [%1], 16;\n" :: "r"(dst), "l"(src));
}
__device__ __forceinline__ void cp_commit() {
    asm volatile("cp.async.commit_group;\n" ::: "memory");
}
__device__ __forceinline__ void cp_wait1() {
    asm volatile("cp.async.wait_group 1;\n" ::: "memory");
}
__device__ __forceinline__ void ldsm_x4(uint32_t* r, unsigned addr) {
    asm volatile("ldmatrix.sync.aligned.m8n8.x4.shared.b16 {%0,%1,%2,%3}, [%4];\n"
                 : "=r"(r[0]), "=r"(r[1]), "=r"(r[2]), "=r"(r[3]) : "r"(addr));
}
__device__ __forceinline__ void ldsm_x4_t(uint32_t* r, unsigned addr) {
    asm volatile("ldmatrix.sync.aligned.m8n8.x4.trans.shared.b16 {%0,%1,%2,%3}, [%4];\n"
                 : "=r"(r[0]), "=r"(r[1]), "=r"(r[2]), "=r"(r[3]) : "r"(addr));
}
__device__ __forceinline__ void mma16816(float* c, const uint32_t* a, uint32_t b0, uint32_t b1) {
    asm volatile("mma.sync.aligned.m16n8k16.row.col.f32.f16.f16.f32 "
                 "{%0,%1,%2,%3},{%4,%5,%6,%7},{%8,%9},{%0,%1,%2,%3};\n"
                 : "+f"(c[0]), "+f"(c[1]), "+f"(c[2]), "+f"(c[3])
                 : "r"(a[0]), "r"(a[1]), "r"(a[2]), "r"(a[3]), "r"(b0), "r"(b1));
}

// ---------------- fp32 -> fp16 convert ----------------
__global__ void cvt_f32_f16(const float* __restrict__ src, __half* __restrict__ dst, int n) {
    int i = (blockIdx.x * blockDim.x + threadIdx.x) * 4;
    if (i >= n) return;
    float4 v = *(const float4*)(src + i);
    *(__half2*)(dst + i)     = __floats2half2_rn(v.x, v.y);
    *(__half2*)(dst + i + 2) = __floats2half2_rn(v.z, v.w);
}

// pack b1 (8x4096) ++ bg1 (4096) into one bias table
__global__ void pack_bias(const float* __restrict__ b1, const float* __restrict__ bg1,
                          float* __restrict__ dst) {
    int i = blockIdx.x * 256 + threadIdx.x;
    if (i < NEXP * DHID) dst[i] = b1[i];
    else if (i < (NEXP + 1) * DHID) dst[i] = bg1[i - NEXP * DHID];
}

// ---------------- gating softmax ----------------
__global__ void __launch_bounds__(256) gate_kernel(
    const __half* __restrict__ Hg, const float* __restrict__ Wg2,
    const float* __restrict__ bg2, float* __restrict__ gate)
{
    extern __shared__ float sW[];   // [8][4096] transposed
    const int tid = threadIdx.x;
    for (int i = tid; i < DHID * NEXP; i += 256) {
        int k = i >> 3, j = i & 7;
        sW[j * DHID + k] = Wg2[i];
    }
    __syncthreads();
    const int warp = tid >> 5, lane = tid & 31;
    const int row = blockIdx.x * 8 + warp;
    const __half2* h2 = (const __half2*)(Hg + (long long)row * DHID);
    float a[NEXP];
#pragma unroll
    for (int j = 0; j < NEXP; j++) a[j] = 0.f;
    for (int k2 = lane; k2 < DHID / 2; k2 += 32) {
        float2 xv = __half22float2(h2[k2]);
#pragma unroll
        for (int j = 0; j < NEXP; j++)
            a[j] += xv.x * sW[j * DHID + 2 * k2] + xv.y * sW[j * DHID + 2 * k2 + 1];
    }
#pragma unroll
    for (int j = 0; j < NEXP; j++)
#pragma unroll
        for (int o = 16; o > 0; o >>= 1) a[j] += __shfl_xor_sync(0xffffffffu, a[j], o);
    float m = -1e30f;
#pragma unroll
    for (int j = 0; j < NEXP; j++) { a[j] += bg2[j]; m = fmaxf(m, a[j]); }
    float ex[NEXP], s = 0.f;
#pragma unroll
    for (int j = 0; j < NEXP; j++) { ex[j] = expf(a[j] - m); s += ex[j]; }
    if (lane < NEXP) gate[row * NEXP + lane] = ex[lane] / s;
}

// out[b][o] = sum_e gate[b][e] * (part[e][b][o] + b2[e][o])
__global__ void __launch_bounds__(256) reduce_kernel(
    const float* __restrict__ part, const float* __restrict__ gate,
    const float* __restrict__ b2, float* __restrict__ out)
{
    const long long i = ((long long)blockIdx.x * 256 + threadIdx.x) * 4;
    const int row = (int)(i >> 10);            // DOUT = 1024
    const int col = (int)(i & 1023);
    const float* gr = gate + row * NEXP;
    float4 s = make_float4(0.f, 0.f, 0.f, 0.f);
#pragma unroll
    for (int e = 0; e < NEXP; e++) {
        const float g = gr[e];
        float4 p = *(const float4*)(part + (long long)e * TOKENS * DOUT + i);
        float4 bb = *(const float4*)(b2 + e * DOUT + col);
        s.x += g * (p.x + bb.x);
        s.y += g * (p.y + bb.y);
        s.z += g * (p.z + bb.z);
        s.w += g * (p.w + bb.w);
    }
    *(float4*)(out + i) = s;
}

// ---------------- fused fp16 GEMM (R8 core) ----------------
// A: [M][K] row-major fp16.  B: [K][N] row-major fp16.
// MODE 1: C = relu(A@B + bias_e)  -> fp16  (layer-1 incl. gating as e=8; z-slab on B/bias/C)
// MODE 2: C = A_e@B_e             -> fp32  (layer-2 partial, z-slab on A/B/C, K=4096)
constexpr int BM = 128, BN = 128, BK = 64, STAGES = 3;
constexpr int ASTR = BK + 8;          // 72 halves
constexpr int BSTR = BN + 8;          // 136 halves
constexpr int A_TILE = BM * ASTR;     // halves
constexpr int B_TILE = BK * BSTR;
constexpr int SMEM_BYTES = STAGES * (A_TILE + B_TILE) * 2;   // 107,520 B

template <int MODE>
__global__ void __launch_bounds__(256) moe_gemm(
    const __half* __restrict__ Abase, long long aSlab, int lda,
    const __half* __restrict__ Bbase, long long bStride, int ldb,
    const float* __restrict__ biasBase, long long biasStride,
    void* __restrict__ Cbase, long long cStride, int ldc,
    int K)
{
    extern __shared__ __half sm_[];
    __half* As = sm_;
    __half* Bs = sm_ + STAGES * A_TILE;

    const int tid  = threadIdx.x;
    const int lane = tid & 31;
    const int warp = tid >> 5;
    const int wm = warp >> 1, wn = warp & 1;   // 4x2 warp grid, warp tile 32x64
    const int bm0 = blockIdx.y * BM;
    const int bn0 = blockIdx.x * BN;
    const int e   = blockIdx.z;

    const __half* Amat = Abase + (MODE == 2 ? (long long)e * aSlab : 0LL);
    const __half* Bmat = Bbase + (long long)e * bStride;

    const unsigned sA0 = (unsigned)__cvta_generic_to_shared(As);
    const unsigned sB0 = (unsigned)__cvta_generic_to_shared(Bs);

    float acc[2][8][4];
#pragma unroll
    for (int a = 0; a < 2; a++)
#pragma unroll
        for (int b = 0; b < 8; b++)
#pragma unroll
            for (int c = 0; c < 4; c++) acc[a][b][c] = 0.f;

    const int KT = K / BK;

    auto load_tile = [&](int kt, int buf) {
        const int k0 = kt * BK;
        const __half* aSrc = Amat + k0;
        const __half* bSrc = Bmat + (long long)k0 * ldb + bn0;
        const unsigned da = sA0 + buf * (A_TILE * 2);
        const unsigned db = sB0 + buf * (B_TILE * 2);
#pragma unroll
        for (int i = 0; i < 4; i++) {
            int c = tid + i * 256;
            int r = c >> 3, c8 = (c & 7) << 3;
            cp_async16(da + (unsigned)(r * ASTR + c8) * 2,
                       aSrc + (long long)(bm0 + r) * lda + c8);
        }
#pragma unroll
        for (int i = 0; i < 4; i++) {
            int c = tid + i * 256;
            int r = c >> 4, c16 = (c & 15) << 3;
            cp_async16(db + (unsigned)(r * BSTR + c16) * 2,
                       bSrc + (long long)r * ldb + c16);
        }
        cp_commit();
    };

    load_tile(0, 0);
    load_tile(1, 1);

    const int lr = lane & 15;
    const int lc = (lane >> 4) << 3;

    for (int kt = 0; kt < KT; kt++) {
        cp_wait1();
        __syncthreads();
        const int nt = kt + 2;
        if (nt < KT) load_tile(nt, nt % STAGES);
        else         cp_commit();     // empty group keeps wait accounting aligned

        const int buf = kt % STAGES;
        const unsigned aB = sA0 + buf * (A_TILE * 2);
        const unsigned bB = sB0 + buf * (B_TILE * 2);
#pragma unroll
        for (int ks = 0; ks < BK / 16; ks++) {
            uint32_t af[2][4];
#pragma unroll
            for (int mb = 0; mb < 2; mb++)
                ldsm_x4(af[mb], aB + (unsigned)((wm * 32 + mb * 16 + lr) * ASTR + ks * 16 + lc) * 2);
            uint32_t bf[4][4];
#pragma unroll
            for (int nb = 0; nb < 4; nb++)
                ldsm_x4_t(bf[nb], bB + (unsigned)((ks * 16 + lr) * BSTR + wn * 64 + nb * 16 + lc) * 2);
#pragma unroll
            for (int mb = 0; mb < 2; mb++)
#pragma unroll
                for (int nb = 0; nb < 4; nb++) {
                    mma16816(acc[mb][2 * nb],     af[mb], bf[nb][0], bf[nb][1]);
                    mma16816(acc[mb][2 * nb + 1], af[mb], bf[nb][2], bf[nb][3]);
                }
        }
    }

    // -------- epilogue --------
    const int g  = lane >> 2;
    const int tg = lane & 3;

    if constexpr (MODE == 1) {
        __half* C = (__half*)Cbase + (long long)e * cStride;
        const float* bias = biasBase + (long long)e * biasStride;
#pragma unroll
        for (int mb = 0; mb < 2; mb++)
#pragma unroll
            for (int i = 0; i < 2; i++) {
                const int row = bm0 + wm * 32 + mb * 16 + g + i * 8;
#pragma unroll
                for (int nb = 0; nb < 8; nb++) {
                    const int col = bn0 + wn * 64 + nb * 8 + tg * 2;
                    float v0 = fmaxf(acc[mb][nb][2 * i + 0] + bias[col],     0.f);
                    float v1 = fmaxf(acc[mb][nb][2 * i + 1] + bias[col + 1], 0.f);
                    *(__half2*)(C + (long long)row * ldc + col) = __floats2half2_rn(v0, v1);
                }
            }
    } else {
        float* C = (float*)Cbase + (long long)e * cStride;
#pragma unroll
        for (int mb = 0; mb < 2; mb++)
#pragma unroll
            for (int i = 0; i < 2; i++) {
                const int row = bm0 + wm * 32 + mb * 16 + g + i * 8;
#pragma unroll
                for (int nb = 0; nb < 8; nb++) {
                    const int col = bn0 + wn * 64 + nb * 8 + tg * 2;
                    float2 o;
                    o.x = acc[mb][nb][2 * i + 0];
                    o.y = acc[mb][nb][2 * i + 1];
                    *(float2*)(C + (long long)row * ldc + col) = o;
                }
            }
    }
}

// ---------------- launch ----------------
extern "C" void kernel_launch(void* const* d_in, const int* in_sizes, int n_in,
                              void* d_out, int out_size)
{
    const float* x   = (const float*)d_in[0];
    const float* W1  = (const float*)d_in[1];
    const float* b1  = (const float*)d_in[2];
    const float* W2  = (const float*)d_in[3];
    const float* b2  = (const float*)d_in[4];
    const float* Wg1 = (const float*)d_in[5];
    const float* bg1 = (const float*)d_in[6];
    const float* Wg2 = (const float*)d_in[7];
    const float* bg2 = (const float*)d_in[8];

    __half *xh, *B1, *W2h, *H;
    float *b1a, *gate, *part;
    cudaGetSymbolAddress((void**)&xh,   g_xh);
    cudaGetSymbolAddress((void**)&B1,   g_B1);
    cudaGetSymbolAddress((void**)&W2h,  g_W2h);
    cudaGetSymbolAddress((void**)&H,    g_H);
    cudaGetSymbolAddress((void**)&b1a,  g_b1a);
    cudaGetSymbolAddress((void**)&gate, g_gate);
    cudaGetSymbolAddress((void**)&part, g_part);

    cudaFuncSetAttribute(moe_gemm<1>, cudaFuncAttributeMaxDynamicSharedMemorySize, SMEM_BYTES);
    cudaFuncSetAttribute(moe_gemm<2>, cudaFuncAttributeMaxDynamicSharedMemorySize, SMEM_BYTES);
    cudaFuncSetAttribute(gate_kernel, cudaFuncAttributeMaxDynamicSharedMemorySize, DHID * NEXP * 4);

    // fp32 -> fp16 converts + bias pack
    cvt_f32_f16<<<TOKENS * DIN / 1024, 256>>>(x, xh, TOKENS * DIN);
    cvt_f32_f16<<<NEXP * DIN * DHID / 1024, 256>>>(W1, B1, NEXP * DIN * DHID);
    cvt_f32_f16<<<DIN * DHID / 1024, 256>>>(Wg1, B1 + (long long)NEXP * DIN * DHID, DIN * DHID);
    cvt_f32_f16<<<NEXP * DHID * DOUT / 1024, 256>>>(W2, W2h, NEXP * DHID * DOUT);
    pack_bias<<<((NEXP + 1) * DHID + 255) / 256, 256>>>(b1, bg1, b1a);

    // 1) layer-1, 9 slabs in ONE launch: H[e] = relu(x @ W1[e] + b1[e]); e=8 -> gating hidden
    moe_gemm<1><<<dim3(DHID / BN, TOKENS / BM, NEXP + 1), 256, SMEM_BYTES>>>(
        xh, 0, DIN,
        B1, (long long)DIN * DHID, DHID,
        b1a, DHID,
        H, (long long)TOKENS * DHID, DHID, DIN);

    // 2) gates (from slot 8)
    gate_kernel<<<TOKENS / 8, 256, DHID * NEXP * 4>>>(
        H + (long long)NEXP * TOKENS * DHID, Wg2, bg2, gate);

    // 3) layer-2 split-K over experts: part[e] = H[e] @ W2[e]  (gate deferred)
    moe_gemm<2><<<dim3(DOUT / BN, TOKENS / BM, NEXP), 256, SMEM_BYTES>>>(
        H, (long long)TOKENS * DHID, DHID,
        W2h, (long long)DHID * DOUT, DOUT,
        nullptr, 0,
        part, (long long)TOKENS * DOUT, DOUT, DHID);

    // 4) out = sum_e gate[b,e] * (part[e] + b2[e])
    reduce_kernel<<<TOKENS * DOUT / 1024, 256>>>(part, gate, b2, (float*)d_out);
}

// round 13
// speedup vs baseline: 1.1350x; 1.0051x over previous
#include <cuda_runtime.h>
#include <cuda_fp16.h>
#include <cstdint>

#define TOKENS 4096
#define DIN    1024
#define DHID   4096
#define DOUT   1024
#define NEXP   8

// ---------------- device scratch ----------------
__device__ __half g_xh [TOKENS * DIN];                          // x fp16 [M][K]
__device__ __half g_B1 [(NEXP + 1) * (size_t)DIN * DHID];       // W1 [e][K][N] + Wg1 (e=8), fp16
__device__ __half g_W2h[(size_t)NEXP * DHID * DOUT];            // W2 [e][K][N] fp16
__device__ __half g_H  [(NEXP + 1) * (size_t)TOKENS * DHID];    // H[e][b][h]; slot 8 = gating hidden
__device__ float  g_b1a[(NEXP + 1) * DHID];                     // b1 (e<8) ++ bg1 (e=8)
__device__ float  g_gate[TOKENS * NEXP];

// ---------------- PTX helpers ----------------
__device__ __forceinline__ void cp_async16(unsigned dst, const void* src) {
    asm volatile("cp.async.cg.shared.global [%0], [%1], 16;\n" :: "r"(dst), "l"(src));
}
__device__ __forceinline__ void cp_commit() {
    asm volatile("cp.async.commit_group;\n" ::: "memory");
}
__device__ __forceinline__ void cp_wait1() {
    asm volatile("cp.async.wait_group 1;\n" ::: "memory");
}
__device__ __forceinline__ void ldsm_x4(uint32_t* r, unsigned addr) {
    asm volatile("ldmatrix.sync.aligned.m8n8.x4.shared.b16 {%0,%1,%2,%3}, [%4];\n"
                 : "=r"(r[0]), "=r"(r[1]), "=r"(r[2]), "=r"(r[3]) : "r"(addr));
}
__device__ __forceinline__ void ldsm_x4_t(uint32_t* r, unsigned addr) {
    asm volatile("ldmatrix.sync.aligned.m8n8.x4.trans.shared.b16 {%0,%1,%2,%3}, [%4];\n"
                 : "=r"(r[0]), "=r"(r[1]), "=r"(r[2]), "=r"(r[3]) : "r"(addr));
}
__device__ __forceinline__ void mma16816(float* c, const uint32_t* a, uint32_t b0, uint32_t b1) {
    asm volatile("mma.sync.aligned.m16n8k16.row.col.f32.f16.f16.f32 "
                 "{%0,%1,%2,%3},{%4,%5,%6,%7},{%8,%9},{%0,%1,%2,%3};\n"
                 : "+f"(c[0]), "+f"(c[1]), "+f"(c[2]), "+f"(c[3])
                 : "r"(a[0]), "r"(a[1]), "r"(a[2]), "r"(a[3]), "r"(b0), "r"(b1));
}

// ---------------- fp32 -> fp16 convert (32B/thread) ----------------
__global__ void cvt_f32_f16(const float4* __restrict__ src, __half2* __restrict__ dst, int n4) {
    int i = (blockIdx.x * blockDim.x + threadIdx.x) * 2;   // float4 units
    if (i >= n4) return;
    float4 a = src[i], b = src[i + 1];
    __half2 h[4];
    h[0] = __floats2half2_rn(a.x, a.y);
    h[1] = __floats2half2_rn(a.z, a.w);
    h[2] = __floats2half2_rn(b.x, b.y);
    h[3] = __floats2half2_rn(b.z, b.w);
    *(float4*)(dst + i * 2) = *(float4*)h;   // 16B store of 8 halves
}

// pack b1 (8x4096) ++ bg1 (4096) into one bias table
__global__ void pack_bias(const float* __restrict__ b1, const float* __restrict__ bg1,
                          float* __restrict__ dst) {
    int i = blockIdx.x * 256 + threadIdx.x;
    if (i < NEXP * DHID) dst[i] = b1[i];
    else if (i < (NEXP + 1) * DHID) dst[i] = bg1[i - NEXP * DHID];
}

// ---------------- gating softmax ----------------
__global__ void __launch_bounds__(256) gate_kernel(
    const __half* __restrict__ Hg, const float* __restrict__ Wg2,
    const float* __restrict__ bg2, float* __restrict__ gate)
{
    extern __shared__ float sW[];   // [8][4096] transposed
    const int tid = threadIdx.x;
    for (int i = tid; i < DHID * NEXP; i += 256) {
        int k = i >> 3, j = i & 7;
        sW[j * DHID + k] = Wg2[i];
    }
    __syncthreads();
    const int warp = tid >> 5, lane = tid & 31;
    const int row = blockIdx.x * 8 + warp;
    const __half2* h2 = (const __half2*)(Hg + (long long)row * DHID);
    float a[NEXP];
#pragma unroll
    for (int j = 0; j < NEXP; j++) a[j] = 0.f;
    for (int k2 = lane; k2 < DHID / 2; k2 += 32) {
        float2 xv = __half22float2(h2[k2]);
#pragma unroll
        for (int j = 0; j < NEXP; j++)
            a[j] += xv.x * sW[j * DHID + 2 * k2] + xv.y * sW[j * DHID + 2 * k2 + 1];
    }
#pragma unroll
    for (int j = 0; j < NEXP; j++)
#pragma unroll
        for (int o = 16; o > 0; o >>= 1) a[j] += __shfl_xor_sync(0xffffffffu, a[j], o);
    float m = -1e30f;
#pragma unroll
    for (int j = 0; j < NEXP; j++) { a[j] += bg2[j]; m = fmaxf(m, a[j]); }
    float ex[NEXP], s = 0.f;
#pragma unroll
    for (int j = 0; j < NEXP; j++) { ex[j] = expf(a[j] - m); s += ex[j]; }
    if (lane < NEXP) gate[row * NEXP + lane] = ex[lane] / s;
}

// out[b][o] = sum_j gate[b][j] * b2[j][o]   (initializes d_out before atomic GEMM)
__global__ void __launch_bounds__(256) out_init_kernel(
    const float* __restrict__ gate, const float* __restrict__ b2, float* __restrict__ out)
{
    int b = blockIdx.x;
    float g[NEXP];
#pragma unroll
    for (int j = 0; j < NEXP; j++) g[j] = gate[b * NEXP + j];
    for (int o = threadIdx.x; o < DOUT; o += 256) {
        float s = 0.f;
#pragma unroll
        for (int j = 0; j < NEXP; j++) s += g[j] * b2[j * DOUT + o];
        out[b * DOUT + o] = s;
    }
}

// ---------------- fused fp16 GEMM (R8 core) ----------------
// A: [M][K] row-major fp16.  B: [K][N] row-major fp16.
// MODE 1: C = relu(A@B + bias_e)          -> fp16 (layer-1, 9 z-slabs incl. gating e=8)
// MODE 2: out += gate[b,e] * (A_e@B_e)    -> fp32 atomicAdd (layer-2, z=e, K=4096)
constexpr int BM = 128, BN = 128, BK = 64, STAGES = 3;
constexpr int ASTR = BK + 8;          // 72 halves
constexpr int BSTR = BN + 8;          // 136 halves
constexpr int A_TILE = BM * ASTR;     // halves
constexpr int B_TILE = BK * BSTR;
constexpr int SMEM_BYTES = STAGES * (A_TILE + B_TILE) * 2;   // 107,520 B

template <int MODE>
__global__ void __launch_bounds__(256) moe_gemm(
    const __half* __restrict__ Abase, long long aSlab, int lda,
    const __half* __restrict__ Bbase, long long bStride, int ldb,
    const float* __restrict__ biasBase, long long biasStride,
    const float* __restrict__ gate,
    void* __restrict__ Cbase, long long cStride, int ldc,
    int K)
{
    extern __shared__ __half sm_[];
    __half* As = sm_;
    __half* Bs = sm_ + STAGES * A_TILE;

    const int tid  = threadIdx.x;
    const int lane = tid & 31;
    const int warp = tid >> 5;
    const int wm = warp >> 1, wn = warp & 1;   // 4x2 warp grid, warp tile 32x64
    const int bm0 = blockIdx.y * BM;
    const int bn0 = blockIdx.x * BN;
    const int e   = blockIdx.z;

    const __half* Amat = Abase + (MODE == 2 ? (long long)e * aSlab : 0LL);
    const __half* Bmat = Bbase + (long long)e * bStride;

    const unsigned sA0 = (unsigned)__cvta_generic_to_shared(As);
    const unsigned sB0 = (unsigned)__cvta_generic_to_shared(Bs);

    float acc[2][8][4];
#pragma unroll
    for (int a = 0; a < 2; a++)
#pragma unroll
        for (int b = 0; b < 8; b++)
#pragma unroll
            for (int c = 0; c < 4; c++) acc[a][b][c] = 0.f;

    const int KT = K / BK;

    auto load_tile = [&](int kt, int buf) {
        const int k0 = kt * BK;
        const __half* aSrc = Amat + k0;
        const __half* bSrc = Bmat + (long long)k0 * ldb + bn0;
        const unsigned da = sA0 + buf * (A_TILE * 2);
        const unsigned db = sB0 + buf * (B_TILE * 2);
#pragma unroll
        for (int i = 0; i < 4; i++) {
            int c = tid + i * 256;
            int r = c >> 3, c8 = (c & 7) << 3;
            cp_async16(da + (unsigned)(r * ASTR + c8) * 2,
                       aSrc + (long long)(bm0 + r) * lda + c8);
        }
#pragma unroll
        for (int i = 0; i < 4; i++) {
            int c = tid + i * 256;
            int r = c >> 4, c16 = (c & 15) << 3;
            cp_async16(db + (unsigned)(r * BSTR + c16) * 2,
                       bSrc + (long long)r * ldb + c16);
        }
        cp_commit();
    };

    load_tile(0, 0);
    load_tile(1, 1);

    const int lr = lane & 15;
    const int lc = (lane >> 4) << 3;

    for (int kt = 0; kt < KT; kt++) {
        cp_wait1();
        __syncthreads();
        const int nt = kt + 2;
        if (nt < KT) load_tile(nt, nt % STAGES);
        else         cp_commit();     // empty group keeps wait accounting aligned

        const int buf = kt % STAGES;
        const unsigned aB = sA0 + buf * (A_TILE * 2);
        const unsigned bB = sB0 + buf * (B_TILE * 2);
#pragma unroll
        for (int ks = 0; ks < BK / 16; ks++) {
            uint32_t af[2][4];
#pragma unroll
            for (int mb = 0; mb < 2; mb++)
                ldsm_x4(af[mb], aB + (unsigned)((wm * 32 + mb * 16 + lr) * ASTR + ks * 16 + lc) * 2);
            uint32_t bf[4][4];
#pragma unroll
            for (int nb = 0; nb < 4; nb++)
                ldsm_x4_t(bf[nb], bB + (unsigned)((ks * 16 + lr) * BSTR + wn * 64 + nb * 16 + lc) * 2);
#pragma unroll
            for (int mb = 0; mb < 2; mb++)
#pragma unroll
                for (int nb = 0; nb < 4; nb++) {
                    mma16816(acc[mb][2 * nb],     af[mb], bf[nb][0], bf[nb][1]);
                    mma16816(acc[mb][2 * nb + 1], af[mb], bf[nb][2], bf[nb][3]);
                }
        }
    }

    // -------- epilogue --------
    const int g  = lane >> 2;
    const int tg = lane & 3;

    if constexpr (MODE == 1) {
        __half* C = (__half*)Cbase + (long long)e * cStride;
        const float* bias = biasBase + (long long)e * biasStride;
#pragma unroll
        for (int mb = 0; mb < 2; mb++)
#pragma unroll
            for (int i = 0; i < 2; i++) {
                const int row = bm0 + wm * 32 + mb * 16 + g + i * 8;
#pragma unroll
                for (int nb = 0; nb < 8; nb++) {
                    const int col = bn0 + wn * 64 + nb * 8 + tg * 2;
                    float v0 = fmaxf(acc[mb][nb][2 * i + 0] + bias[col],     0.f);
                    float v1 = fmaxf(acc[mb][nb][2 * i + 1] + bias[col + 1], 0.f);
                    *(__half2*)(C + (long long)row * ldc + col) = __floats2half2_rn(v0, v1);
                }
            }
    } else {
        float* C = (float*)Cbase;
#pragma unroll
        for (int mb = 0; mb < 2; mb++)
#pragma unroll
            for (int i = 0; i < 2; i++) {
                const int row = bm0 + wm * 32 + mb * 16 + g + i * 8;
                const float gv = gate[row * NEXP + e];
#pragma unroll
                for (int nb = 0; nb < 8; nb++) {
                    const int col = bn0 + wn * 64 + nb * 8 + tg * 2;
                    atomicAdd(C + (long long)row * ldc + col,     gv * acc[mb][nb][2 * i + 0]);
                    atomicAdd(C + (long long)row * ldc + col + 1, gv * acc[mb][nb][2 * i + 1]);
                }
            }
    }
}

// ---------------- launch ----------------
extern "C" void kernel_launch(void* const* d_in, const int* in_sizes, int n_in,
                              void* d_out, int out_size)
{
    const float* x   = (const float*)d_in[0];
    const float* W1  = (const float*)d_in[1];
    const float* b1  = (const float*)d_in[2];
    const float* W2  = (const float*)d_in[3];
    const float* b2  = (const float*)d_in[4];
    const float* Wg1 = (const float*)d_in[5];
    const float* bg1 = (const float*)d_in[6];
    const float* Wg2 = (const float*)d_in[7];
    const float* bg2 = (const float*)d_in[8];

    __half *xh, *B1, *W2h, *H;
    float *b1a, *gate;
    cudaGetSymbolAddress((void**)&xh,   g_xh);
    cudaGetSymbolAddress((void**)&B1,   g_B1);
    cudaGetSymbolAddress((void**)&W2h,  g_W2h);
    cudaGetSymbolAddress((void**)&H,    g_H);
    cudaGetSymbolAddress((void**)&b1a,  g_b1a);
    cudaGetSymbolAddress((void**)&gate, g_gate);

    cudaFuncSetAttribute(moe_gemm<1>, cudaFuncAttributeMaxDynamicSharedMemorySize, SMEM_BYTES);
    cudaFuncSetAttribute(moe_gemm<2>, cudaFuncAttributeMaxDynamicSharedMemorySize, SMEM_BYTES);
    cudaFuncSetAttribute(gate_kernel, cudaFuncAttributeMaxDynamicSharedMemorySize, DHID * NEXP * 4);

    // fp32 -> fp16 converts (8 floats/thread) + bias pack
    cvt_f32_f16<<<TOKENS * DIN / 2048, 256>>>((const float4*)x, (__half2*)xh, TOKENS * DIN / 4);
    cvt_f32_f16<<<NEXP * DIN * DHID / 2048, 256>>>((const float4*)W1, (__half2*)B1, NEXP * DIN * DHID / 4);
    cvt_f32_f16<<<DIN * DHID / 2048, 256>>>((const float4*)Wg1,
        (__half2*)(B1 + (long long)NEXP * DIN * DHID), DIN * DHID / 4);
    cvt_f32_f16<<<NEXP * DHID * DOUT / 2048, 256>>>((const float4*)W2, (__half2*)W2h, NEXP * DHID * DOUT / 4);
    pack_bias<<<((NEXP + 1) * DHID + 255) / 256, 256>>>(b1, bg1, b1a);

    // 1) layer-1, 9 slabs in ONE launch: H[e] = relu(x @ W1[e] + b1[e]); e=8 -> gating hidden
    moe_gemm<1><<<dim3(DHID / BN, TOKENS / BM, NEXP + 1), 256, SMEM_BYTES>>>(
        xh, 0, DIN,
        B1, (long long)DIN * DHID, DHID,
        b1a, DHID, nullptr,
        H, (long long)TOKENS * DHID, DHID, DIN);

    // 2) gates (from slot 8)
    gate_kernel<<<TOKENS / 8, 256, DHID * NEXP * 4>>>(
        H + (long long)NEXP * TOKENS * DHID, Wg2, bg2, gate);

    // 3) init out = sum_e gate*b2 (replay-safe re-initialization)
    out_init_kernel<<<TOKENS, 256>>>(gate, b2, (float*)d_out);

    // 4) layer-2 split over experts, gate-scaled atomic accumulation into out
    moe_gemm<2><<<dim3(DOUT / BN, TOKENS / BM, NEXP), 256, SMEM_BYTES>>>(
        H, (long long)TOKENS * DHID, DHID,
        W2h, (long long)DHID * DOUT, DOUT,
        nullptr, 0, gate,
        d_out, 0, DOUT, DHID);
}

// round 14
// speedup vs baseline: 1.1470x; 1.0106x over previous
#include <cuda_runtime.h>
#include <cuda_fp16.h>
#include <cstdint>

#define TOKENS 4096
#define DIN    1024
#define DHID   4096
#define DOUT   1024
#define NEXP   8

// ---------------- device scratch ----------------
__device__ __half g_xh [TOKENS * DIN];                          // x fp16 [M][K]
__device__ __half g_B1 [(NEXP + 1) * (size_t)DIN * DHID];       // W1 [e][K][N] + Wg1 (e=8), fp16
__device__ __half g_W2h[(size_t)NEXP * DHID * DOUT];            // W2 [e][K][N] fp16
__device__ __half g_H  [(NEXP + 1) * (size_t)TOKENS * DHID];    // H[e][b][h]; slot 8 = gating hidden
__device__ float  g_b1a[(NEXP + 1) * DHID];                     // b1 (e<8) ++ bg1 (e=8)
__device__ float  g_gate[TOKENS * NEXP];

// ---------------- PTX helpers ----------------
__device__ __forceinline__ void cp_async16(unsigned dst, const void* src) {
    asm volatile("cp.async.cg.shared.global [%0], [%1], 16;\n" :: "r"(dst), "l"(src));
}
__device__ __forceinline__ void cp_commit() {
    asm volatile("cp.async.commit_group;\n" ::: "memory");
}
__device__ __forceinline__ void cp_wait1() {
    asm volatile("cp.async.wait_group 1;\n" ::: "memory");
}
__device__ __forceinline__ void ldsm_x4(uint32_t* r, unsigned addr) {
    asm volatile("ldmatrix.sync.aligned.m8n8.x4.shared.b16 {%0,%1,%2,%3}, [%4];\n"
                 : "=r"(r[0]), "=r"(r[1]), "=r"(r[2]), "=r"(r[3]) : "r"(addr));
}
__device__ __forceinline__ void ldsm_x4_t(uint32_t* r, unsigned addr) {
    asm volatile("ldmatrix.sync.aligned.m8n8.x4.trans.shared.b16 {%0,%1,%2,%3}, [%4];\n"
                 : "=r"(r[0]), "=r"(r[1]), "=r"(r[2]), "=r"(r[3]) : "r"(addr));
}
__device__ __forceinline__ void mma16816(float* c, const uint32_t* a, uint32_t b0, uint32_t b1) {
    asm volatile("mma.sync.aligned.m16n8k16.row.col.f32.f16.f16.f32 "
                 "{%0,%1,%2,%3},{%4,%5,%6,%7},{%8,%9},{%0,%1,%2,%3};\n"
                 : "+f"(c[0]), "+f"(c[1]), "+f"(c[2]), "+f"(c[3])
                 : "r"(a[0]), "r"(a[1]), "r"(a[2]), "r"(a[3]), "r"(b0), "r"(b1));
}

// ---------------- fp32 -> fp16 convert (32B/thread) ----------------
__global__ void cvt_f32_f16(const float4* __restrict__ src, __half2* __restrict__ dst, int n4) {
    int i = (blockIdx.x * blockDim.x + threadIdx.x) * 2;   // float4 units
    if (i >= n4) return;
    float4 a = src[i], b = src[i + 1];
    __half2 h[4];
    h[0] = __floats2half2_rn(a.x, a.y);
    h[1] = __floats2half2_rn(a.z, a.w);
    h[2] = __floats2half2_rn(b.x, b.y);
    h[3] = __floats2half2_rn(b.z, b.w);
    *(float4*)(dst + i * 2) = *(float4*)h;   // 16B store of 8 halves
}

// pack b1 (8x4096) ++ bg1 (4096) into one bias table
__global__ void pack_bias(const float* __restrict__ b1, const float* __restrict__ bg1,
                          float* __restrict__ dst) {
    int i = blockIdx.x * 256 + threadIdx.x;
    if (i < NEXP * DHID) dst[i] = b1[i];
    else if (i < (NEXP + 1) * DHID) dst[i] = bg1[i - NEXP * DHID];
}

// ---------------- fused gating softmax + out initialization ----------------
// One warp handles 8 token rows:
//   logits[r][j] = sum_k Hg[row][k] * Wg2[k][j] + bg2[j]   (no smem; Wg2 reused x8 in regs)
//   gate[row][j] = softmax_j(logits)
//   out[row][o]  = sum_j gate[row][j] * b2[j][o]           (pre-atomic init of d_out)
__global__ void __launch_bounds__(256) gate_out_kernel(
    const __half* __restrict__ Hg, const float* __restrict__ Wg2,
    const float* __restrict__ bg2, const float* __restrict__ b2,
    float* __restrict__ gate, float* __restrict__ out)
{
    const int warp = threadIdx.x >> 5, lane = threadIdx.x & 31;
    const int row0 = (blockIdx.x * 8 + warp) * 8;       // 8 rows per warp

    float a[8][8];
#pragma unroll
    for (int r = 0; r < 8; r++)
#pragma unroll
        for (int j = 0; j < NEXP; j++) a[r][j] = 0.f;

    for (int k2 = lane; k2 < DHID / 2; k2 += 32) {
        const float4* w = (const float4*)(Wg2 + (2 * k2) * NEXP);
        float4 w00 = w[0], w01 = w[1];   // Wg2 row 2*k2
        float4 w10 = w[2], w11 = w[3];   // Wg2 row 2*k2+1
#pragma unroll
        for (int r = 0; r < 8; r++) {
            float2 xv = __half22float2(
                *(const __half2*)(Hg + (long long)(row0 + r) * DHID + 2 * k2));
            a[r][0] += xv.x * w00.x + xv.y * w10.x;
            a[r][1] += xv.x * w00.y + xv.y * w10.y;
            a[r][2] += xv.x * w00.z + xv.y * w10.z;
            a[r][3] += xv.x * w00.w + xv.y * w10.w;
            a[r][4] += xv.x * w01.x + xv.y * w11.x;
            a[r][5] += xv.x * w01.y + xv.y * w11.y;
            a[r][6] += xv.x * w01.z + xv.y * w11.z;
            a[r][7] += xv.x * w01.w + xv.y * w11.w;
        }
    }
    // butterfly reduce: afterwards every lane holds the full 8x8 logit block
#pragma unroll
    for (int o = 16; o > 0; o >>= 1)
#pragma unroll
        for (int r = 0; r < 8; r++)
#pragma unroll
            for (int j = 0; j < NEXP; j++)
                a[r][j] += __shfl_xor_sync(0xffffffffu, a[r][j], o);

    float bg[NEXP];
#pragma unroll
    for (int j = 0; j < NEXP; j++) bg[j] = bg2[j];

#pragma unroll
    for (int r = 0; r < 8; r++) {
        float m = -1e30f;
#pragma unroll
        for (int j = 0; j < NEXP; j++) { a[r][j] += bg[j]; m = fmaxf(m, a[r][j]); }
        float s = 0.f;
#pragma unroll
        for (int j = 0; j < NEXP; j++) { a[r][j] = __expf(a[r][j] - m); s += a[r][j]; }
        const float inv = 1.f / s;
#pragma unroll
        for (int j = 0; j < NEXP; j++) a[r][j] *= inv;
    }

    // gate stores (lane j writes expert j, all lanes hold identical values)
#pragma unroll
    for (int r = 0; r < 8; r++)
#pragma unroll
        for (int j = 0; j < NEXP; j++)
            if (lane == j) gate[(row0 + r) * NEXP + j] = a[r][j];

    // out init: out[row] = sum_j gate[row][j] * b2[j][:]
#pragma unroll
    for (int r = 0; r < 8; r++) {
        float* op = out + (long long)(row0 + r) * DOUT;
        for (int o = lane * 4; o < DOUT; o += 128) {
            float4 s = make_float4(0.f, 0.f, 0.f, 0.f);
#pragma unroll
            for (int j = 0; j < NEXP; j++) {
                float4 bb = *(const float4*)(b2 + j * DOUT + o);
                s.x += a[r][j] * bb.x;
                s.y += a[r][j] * bb.y;
                s.z += a[r][j] * bb.z;
                s.w += a[r][j] * bb.w;
            }
            *(float4*)(op + o) = s;
        }
    }
}

// ---------------- fused fp16 GEMM (R8 core) ----------------
// A: [M][K] row-major fp16.  B: [K][N] row-major fp16.
// MODE 1: C = relu(A@B + bias_e)          -> fp16 (layer-1, 9 z-slabs incl. gating e=8)
// MODE 2: out += gate[b,e] * (A_e@B_e)    -> fp32 atomicAdd (layer-2, z=e, K=4096)
constexpr int BM = 128, BN = 128, BK = 64, STAGES = 3;
constexpr int ASTR = BK + 8;          // 72 halves
constexpr int BSTR = BN + 8;          // 136 halves
constexpr int A_TILE = BM * ASTR;     // halves
constexpr int B_TILE = BK * BSTR;
constexpr int SMEM_BYTES = STAGES * (A_TILE + B_TILE) * 2;   // 107,520 B

template <int MODE>
__global__ void __launch_bounds__(256) moe_gemm(
    const __half* __restrict__ Abase, long long aSlab, int lda,
    const __half* __restrict__ Bbase, long long bStride, int ldb,
    const float* __restrict__ biasBase, long long biasStride,
    const float* __restrict__ gate,
    void* __restrict__ Cbase, long long cStride, int ldc,
    int K)
{
    extern __shared__ __half sm_[];
    __half* As = sm_;
    __half* Bs = sm_ + STAGES * A_TILE;

    const int tid  = threadIdx.x;
    const int lane = tid & 31;
    const int warp = tid >> 5;
    const int wm = warp >> 1, wn = warp & 1;   // 4x2 warp grid, warp tile 32x64
    const int bm0 = blockIdx.y * BM;
    const int bn0 = blockIdx.x * BN;
    const int e   = blockIdx.z;

    const __half* Amat = Abase + (MODE == 2 ? (long long)e * aSlab : 0LL);
    const __half* Bmat = Bbase + (long long)e * bStride;

    const unsigned sA0 = (unsigned)__cvta_generic_to_shared(As);
    const unsigned sB0 = (unsigned)__cvta_generic_to_shared(Bs);

    float acc[2][8][4];
#pragma unroll
    for (int a = 0; a < 2; a++)
#pragma unroll
        for (int b = 0; b < 8; b++)
#pragma unroll
            for (int c = 0; c < 4; c++) acc[a][b][c] = 0.f;

    const int KT = K / BK;

    auto load_tile = [&](int kt, int buf) {
        const int k0 = kt * BK;
        const __half* aSrc = Amat + k0;
        const __half* bSrc = Bmat + (long long)k0 * ldb + bn0;
        const unsigned da = sA0 + buf * (A_TILE * 2);
        const unsigned db = sB0 + buf * (B_TILE * 2);
#pragma unroll
        for (int i = 0; i < 4; i++) {
            int c = tid + i * 256;
            int r = c >> 3, c8 = (c & 7) << 3;
            cp_async16(da + (unsigned)(r * ASTR + c8) * 2,
                       aSrc + (long long)(bm0 + r) * lda + c8);
        }
#pragma unroll
        for (int i = 0; i < 4; i++) {
            int c = tid + i * 256;
            int r = c >> 4, c16 = (c & 15) << 3;
            cp_async16(db + (unsigned)(r * BSTR + c16) * 2,
                       bSrc + (long long)r * ldb + c16);
        }
        cp_commit();
    };

    load_tile(0, 0);
    load_tile(1, 1);

    const int lr = lane & 15;
    const int lc = (lane >> 4) << 3;

    for (int kt = 0; kt < KT; kt++) {
        cp_wait1();
        __syncthreads();
        const int nt = kt + 2;
        if (nt < KT) load_tile(nt, nt % STAGES);
        else         cp_commit();     // empty group keeps wait accounting aligned

        const int buf = kt % STAGES;
        const unsigned aB = sA0 + buf * (A_TILE * 2);
        const unsigned bB = sB0 + buf * (B_TILE * 2);
#pragma unroll
        for (int ks = 0; ks < BK / 16; ks++) {
            uint32_t af[2][4];
#pragma unroll
            for (int mb = 0; mb < 2; mb++)
                ldsm_x4(af[mb], aB + (unsigned)((wm * 32 + mb * 16 + lr) * ASTR + ks * 16 + lc) * 2);
            uint32_t bf[4][4];
#pragma unroll
            for (int nb = 0; nb < 4; nb++)
                ldsm_x4_t(bf[nb], bB + (unsigned)((ks * 16 + lr) * BSTR + wn * 64 + nb * 16 + lc) * 2);
#pragma unroll
            for (int mb = 0; mb < 2; mb++)
#pragma unroll
                for (int nb = 0; nb < 4; nb++) {
                    mma16816(acc[mb][2 * nb],     af[mb], bf[nb][0], bf[nb][1]);
                    mma16816(acc[mb][2 * nb + 1], af[mb], bf[nb][2], bf[nb][3]);
                }
        }
    }

    // -------- epilogue --------
    const int g  = lane >> 2;
    const int tg = lane & 3;

    if constexpr (MODE == 1) {
        __half* C = (__half*)Cbase + (long long)e * cStride;
        const float* bias = biasBase + (long long)e * biasStride;
#pragma unroll
        for (int mb = 0; mb < 2; mb++)
#pragma unroll
            for (int i = 0; i < 2; i++) {
                const int row = bm0 + wm * 32 + mb * 16 + g + i * 8;
#pragma unroll
                for (int nb = 0; nb < 8; nb++) {
                    const int col = bn0 + wn * 64 + nb * 8 + tg * 2;
                    float v0 = fmaxf(acc[mb][nb][2 * i + 0] + bias[col],     0.f);
                    float v1 = fmaxf(acc[mb][nb][2 * i + 1] + bias[col + 1], 0.f);
                    *(__half2*)(C + (long long)row * ldc + col) = __floats2half2_rn(v0, v1);
                }
            }
    } else {
        float* C = (float*)Cbase;
#pragma unroll
        for (int mb = 0; mb < 2; mb++)
#pragma unroll
            for (int i = 0; i < 2; i++) {
                const int row = bm0 + wm * 32 + mb * 16 + g + i * 8;
                const float gv = gate[row * NEXP + e];
#pragma unroll
                for (int nb = 0; nb < 8; nb++) {
                    const int col = bn0 + wn * 64 + nb * 8 + tg * 2;
                    atomicAdd(C + (long long)row * ldc + col,     gv * acc[mb][nb][2 * i + 0]);
                    atomicAdd(C + (long long)row * ldc + col + 1, gv * acc[mb][nb][2 * i + 1]);
                }
            }
    }
}

// ---------------- launch ----------------
extern "C" void kernel_launch(void* const* d_in, const int* in_sizes, int n_in,
                              void* d_out, int out_size)
{
    const float* x   = (const float*)d_in[0];
    const float* W1  = (const float*)d_in[1];
    const float* b1  = (const float*)d_in[2];
    const float* W2  = (const float*)d_in[3];
    const float* b2  = (const float*)d_in[4];
    const float* Wg1 = (const float*)d_in[5];
    const float* bg1 = (const float*)d_in[6];
    const float* Wg2 = (const float*)d_in[7];
    const float* bg2 = (const float*)d_in[8];

    __half *xh, *B1, *W2h, *H;
    float *b1a, *gate;
    cudaGetSymbolAddress((void**)&xh,   g_xh);
    cudaGetSymbolAddress((void**)&B1,   g_B1);
    cudaGetSymbolAddress((void**)&W2h,  g_W2h);
    cudaGetSymbolAddress((void**)&H,    g_H);
    cudaGetSymbolAddress((void**)&b1a,  g_b1a);
    cudaGetSymbolAddress((void**)&gate, g_gate);

    cudaFuncSetAttribute(moe_gemm<1>, cudaFuncAttributeMaxDynamicSharedMemorySize, SMEM_BYTES);
    cudaFuncSetAttribute(moe_gemm<2>, cudaFuncAttributeMaxDynamicSharedMemorySize, SMEM_BYTES);

    // fp32 -> fp16 converts (8 floats/thread) + bias pack
    cvt_f32_f16<<<TOKENS * DIN / 2048, 256>>>((const float4*)x, (__half2*)xh, TOKENS * DIN / 4);
    cvt_f32_f16<<<NEXP * DIN * DHID / 2048, 256>>>((const float4*)W1, (__half2*)B1, NEXP * DIN * DHID / 4);
    cvt_f32_f16<<<DIN * DHID / 2048, 256>>>((const float4*)Wg1,
        (__half2*)(B1 + (long long)NEXP * DIN * DHID), DIN * DHID / 4);
    cvt_f32_f16<<<NEXP * DHID * DOUT / 2048, 256>>>((const float4*)W2, (__half2*)W2h, NEXP * DHID * DOUT / 4);
    pack_bias<<<((NEXP + 1) * DHID + 255) / 256, 256>>>(b1, bg1, b1a);

    // 1) layer-1, 9 slabs in ONE launch: H[e] = relu(x @ W1[e] + b1[e]); e=8 -> gating hidden
    moe_gemm<1><<<dim3(DHID / BN, TOKENS / BM, NEXP + 1), 256, SMEM_BYTES>>>(
        xh, 0, DIN,
        B1, (long long)DIN * DHID, DHID,
        b1a, DHID, nullptr,
        H, (long long)TOKENS * DHID, DHID, DIN);

    // 2) fused gates + out init (from slot 8)
    gate_out_kernel<<<TOKENS / 64, 256>>>(
        H + (long long)NEXP * TOKENS * DHID, Wg2, bg2, b2, gate, (float*)d_out);

    // 3) layer-2 split over experts, gate-scaled atomic accumulation into out
    moe_gemm<2><<<dim3(DOUT / BN, TOKENS / BM, NEXP), 256, SMEM_BYTES>>>(
        H, (long long)TOKENS * DHID, DHID,
        W2h, (long long)DHID * DOUT, DOUT,
        nullptr, 0, gate,
        d_out, 0, DOUT, DHID);
}